// round 1
// baseline (speedup 1.0000x reference)
#include <cuda_runtime.h>
#include <math.h>

// Problem constants
#define T_LEN    8192
#define D_DIM    128
#define N_DIM    32
#define CHN      (N_DIM * D_DIM)         // 4096 channels
#define L_CHUNK  64
#define C_CHUNKS (T_LEN / L_CHUNK)       // 128 chunks

// Scratch: chunk summaries + chunk-start states (device globals, no allocs)
__device__ float g_sa[C_CHUNKS * CHN];   // local h_a scan-from-zero at chunk end
__device__ float g_q0[C_CHUNKS * CHN];   // local h_v scan-from-zero (a=0) at chunk end
__device__ float g_U [C_CHUNKS * CHN];   // sum of u_i over chunk
__device__ float g_as[C_CHUNKS * CHN];   // exact h_a at chunk start
__device__ float g_vs[C_CHUNKS * CHN];   // exact h_v at chunk start

// ---------------------------------------------------------------------------
// Kernel 1: per-(chunk, channel) summaries.
// grid = (C_CHUNKS, N_DIM), block = D_DIM threads (one per d).
// For chunk starting state (a, v):
//   h_a_end = beta^L * a + s_a
//   h_v_end = beta^L * v + q0 + (-2*alpha*beta^L*U)*a + beta^L*(1-beta^L)*a^2
// ---------------------------------------------------------------------------
__global__ void ema_summary(const float* __restrict__ x,
                            const float* __restrict__ alpha) {
    const int d  = threadIdx.x;
    const int c  = blockIdx.x;
    const int n  = blockIdx.y;
    const int ch = n * D_DIM + d;

    const float al = alpha[ch];
    const float be = 1.0f - al;

    float p = 0.0f;   // local h_a from zero
    float r = 0.0f;   // local h_v from zero (q0 accumulator)
    float U = 0.0f;   // sum of u_i

    const float* xp = x + (size_t)c * L_CHUNK * D_DIM + d;
    #pragma unroll 8
    for (int i = 0; i < L_CHUNK; i++) {
        float xv = __ldg(xp + i * D_DIM);
        float u  = xv - p;
        U += u;
        r  = be * fmaf(al * u, u, r);   // r = beta*(r + alpha*u^2)
        p  = fmaf(al, u, p);            // p = p + alpha*u
    }

    const int idx = c * CHN + ch;
    g_sa[idx] = p;
    g_q0[idx] = r;
    g_U [idx] = U;
}

// ---------------------------------------------------------------------------
// Kernel 2: sequential combine over chunks (cheap: 4096 threads x 128 iters).
// Also writes the final-state outputs (hN_a, sqrt(hN_v)).
// ---------------------------------------------------------------------------
__global__ void ema_combine(const float* __restrict__ h_a0,
                            const float* __restrict__ h_sd0,
                            const float* __restrict__ alpha,
                            float* __restrict__ out) {
    const int ch = blockIdx.x * blockDim.x + threadIdx.x;
    if (ch >= CHN) return;

    const float al = alpha[ch];
    const float be = 1.0f - al;

    // P = beta^L via repeated squaring (L = 64 = 2^6)
    float P = be;
    #pragma unroll
    for (int k = 0; k < 6; k++) P = P * P;
    const float q2 = P * (1.0f - P);         // closed form
    const float q1c = -2.0f * al * P;        // q1 = q1c * U

    float a  = h_a0[ch];
    float sd = h_sd0[ch];
    float v  = sd * sd;

    for (int c = 0; c < C_CHUNKS; c++) {
        const int idx = c * CHN + ch;
        g_as[idx] = a;
        g_vs[idx] = v;
        const float sa = g_sa[idx];
        const float q0 = g_q0[idx];
        const float U  = g_U [idx];
        float vn = fmaf(P, v, q0) + fmaf(q2 * a, a, (q1c * U) * a);
        a = fmaf(P, a, sa);
        v = fmaxf(vn, 0.0f);
    }

    // Final states appended after the (T, 2N, D) block
    const size_t base = (size_t)T_LEN * 2 * CHN;
    out[base + ch]       = a;
    out[base + CHN + ch] = sqrtf(v);
}

// ---------------------------------------------------------------------------
// Kernel 3: exact per-chunk replay from exact chunk-start states; writes
// the (T, 2N, D) output. grid = (C_CHUNKS, N_DIM), block = D_DIM.
// Warp-coalesced 128B stores (consecutive d -> consecutive addresses).
// ---------------------------------------------------------------------------
__global__ void ema_output(const float* __restrict__ x,
                           const float* __restrict__ alpha,
                           float* __restrict__ out) {
    const int d  = threadIdx.x;
    const int c  = blockIdx.x;
    const int n  = blockIdx.y;
    const int ch = n * D_DIM + d;
    const int idx = c * CHN + ch;

    const float al = alpha[ch];
    const float be = 1.0f - al;

    float a = g_as[idx];
    float v = g_vs[idx];

    const float* xp = x + (size_t)c * L_CHUNK * D_DIM + d;
    float* oa = out + (size_t)(c * L_CHUNK) * 2 * CHN + n * D_DIM + d;
    float* ov = oa + CHN;

    #pragma unroll 8
    for (int i = 0; i < L_CHUNK; i++) {
        float xv = __ldg(xp + i * D_DIM);
        float dd = xv - a;
        a = fmaf(al, dd, a);                     // h_a update
        v = be * fmaf(al * dd, dd, v);           // h_v update
        const size_t off = (size_t)i * 2 * CHN;
        oa[off] = a;
        ov[off] = sqrtf(v);
    }
}

// ---------------------------------------------------------------------------
// Launch
// ---------------------------------------------------------------------------
extern "C" void kernel_launch(void* const* d_in, const int* in_sizes, int n_in,
                              void* d_out, int out_size) {
    const float* x     = (const float*)d_in[0];
    const float* h_a0  = (const float*)d_in[1];
    const float* h_sd0 = (const float*)d_in[2];
    const float* alpha = (const float*)d_in[3];
    float* out = (float*)d_out;

    dim3 gridCN(C_CHUNKS, N_DIM);
    ema_summary<<<gridCN, D_DIM>>>(x, alpha);
    ema_combine<<<CHN / 128, 128>>>(h_a0, h_sd0, alpha, out);
    ema_output<<<gridCN, D_DIM>>>(x, alpha, out);
}

// round 7
// speedup vs baseline: 1.5400x; 1.5400x over previous
#include <cuda_runtime.h>
#include <math.h>

// Problem constants
#define T_LEN    8192
#define D_DIM    128
#define N_DIM    32
#define CHN      (N_DIM * D_DIM)         // 4096 channels
#define L_CHUNK  64
#define C_CHUNKS (T_LEN / L_CHUNK)       // 128 chunks

// Scratch: chunk summaries + chunk-start states (device globals, no allocs)
__device__ float g_sa[C_CHUNKS * CHN];   // local h_a scan-from-zero at chunk end
__device__ float g_q0[C_CHUNKS * CHN];   // local h_v scan-from-zero (a=0) at chunk end
__device__ float g_U [C_CHUNKS * CHN];   // sum of u_i over chunk
__device__ float g_as[C_CHUNKS * CHN];   // exact h_a at chunk start
__device__ float g_vs[C_CHUNKS * CHN];   // exact h_v at chunk start

__device__ __forceinline__ float fast_sqrt(float x) {
    float y;
    asm("sqrt.approx.f32 %0, %1;" : "=f"(y) : "f"(x));
    return y;
}

// ---------------------------------------------------------------------------
// Kernel 1: per-(chunk, channel) summaries, float4 across d.
// grid = (C_CHUNKS, N_DIM/4), block = 128 threads.
// thread: n_local = tid>>5 (0..3), lane = tid&31 -> d = lane*4 .. lane*4+3
// ---------------------------------------------------------------------------
__global__ void ema_summary(const float4* __restrict__ x,
                            const float4* __restrict__ alpha) {
    const int tid  = threadIdx.x;
    const int lane = tid & 31;
    const int n    = blockIdx.y * 4 + (tid >> 5);
    const int c    = blockIdx.x;
    const int v4   = n * 32 + lane;           // float4 channel index (0..1023)

    const float4 al4 = alpha[v4];
    const float al[4] = {al4.x, al4.y, al4.z, al4.w};
    float be[4], p[4] = {0,0,0,0}, r[4] = {0,0,0,0}, U[4] = {0,0,0,0};
    #pragma unroll
    for (int k = 0; k < 4; k++) be[k] = 1.0f - al[k];

    const float4* xp = x + (size_t)c * L_CHUNK * 32 + lane;
    #pragma unroll 4
    for (int i = 0; i < L_CHUNK; i++) {
        const float4 xv4 = __ldg(xp + i * 32);
        const float xv[4] = {xv4.x, xv4.y, xv4.z, xv4.w};
        #pragma unroll
        for (int k = 0; k < 4; k++) {
            float u = xv[k] - p[k];
            U[k] += u;
            r[k]  = be[k] * fmaf(al[k] * u, u, r[k]);
            p[k]  = fmaf(al[k], u, p[k]);
        }
    }

    const int idx = c * (CHN / 4) + v4;      // float4 index into scratch
    ((float4*)g_sa)[idx] = make_float4(p[0], p[1], p[2], p[3]);
    ((float4*)g_q0)[idx] = make_float4(r[0], r[1], r[2], r[3]);
    ((float4*)g_U )[idx] = make_float4(U[0], U[1], U[2], U[3]);
}

// ---------------------------------------------------------------------------
// Kernel 2: sequential combine over chunks (4096 threads x 128 iters).
// Also writes the final-state outputs (hN_a, sqrt(hN_v)).
// ---------------------------------------------------------------------------
__global__ void ema_combine(const float* __restrict__ h_a0,
                            const float* __restrict__ h_sd0,
                            const float* __restrict__ alpha,
                            float* __restrict__ out) {
    const int ch = blockIdx.x * blockDim.x + threadIdx.x;
    if (ch >= CHN) return;

    const float al = alpha[ch];
    const float be = 1.0f - al;

    // P = beta^L via repeated squaring (L = 64 = 2^6)
    float P = be;
    #pragma unroll
    for (int k = 0; k < 6; k++) P = P * P;
    const float q2  = P * (1.0f - P);        // closed form
    const float q1c = -2.0f * al * P;        // q1 = q1c * U

    float a  = h_a0[ch];
    float sd = h_sd0[ch];
    float v  = sd * sd;

    #pragma unroll 4
    for (int c = 0; c < C_CHUNKS; c++) {
        const int idx = c * CHN + ch;
        __stcg(&g_as[idx], a);               // L2-resident: kernel 3 reads next
        __stcg(&g_vs[idx], v);
        const float sa = __ldg(&g_sa[idx]);
        const float q0 = __ldg(&g_q0[idx]);
        const float U  = __ldg(&g_U [idx]);
        float vn = fmaf(P, v, q0) + fmaf(q2 * a, a, (q1c * U) * a);
        a = fmaf(P, a, sa);
        v = fmaxf(vn, 0.0f);
    }

    // Final states appended after the (T, 2N, D) block
    const size_t base = (size_t)T_LEN * 2 * CHN;
    out[base + ch]       = a;
    out[base + CHN + ch] = fast_sqrt(v);
}

// ---------------------------------------------------------------------------
// Kernel 3: exact per-chunk replay, float4 across d, streaming stores.
// grid = (C_CHUNKS, N_DIM/4), block = 128.
// ---------------------------------------------------------------------------
__global__ void ema_output(const float4* __restrict__ x,
                           const float4* __restrict__ alpha,
                           float4* __restrict__ out) {
    const int tid  = threadIdx.x;
    const int lane = tid & 31;
    const int n    = blockIdx.y * 4 + (tid >> 5);
    const int c    = blockIdx.x;
    const int v4   = n * 32 + lane;
    const int idx  = c * (CHN / 4) + v4;

    const float4 al4 = alpha[v4];
    const float al[4] = {al4.x, al4.y, al4.z, al4.w};
    float be[4];
    #pragma unroll
    for (int k = 0; k < 4; k++) be[k] = 1.0f - al[k];

    const float4 a4 = ((const float4*)g_as)[idx];
    const float4 w4 = ((const float4*)g_vs)[idx];
    float a[4] = {a4.x, a4.y, a4.z, a4.w};
    float v[4] = {w4.x, w4.y, w4.z, w4.w};

    const float4* xp = x + (size_t)c * L_CHUNK * 32 + lane;
    float4* oa = out + (size_t)(c * L_CHUNK) * 2 * (CHN / 4) + v4;
    float4* ov = oa + (CHN / 4);

    int ooff = 0;                                  // int stride, no 64-bit mul
    #pragma unroll 4
    for (int i = 0; i < L_CHUNK; i++) {
        const float4 xv4 = __ldg(xp + i * 32);
        const float xv[4] = {xv4.x, xv4.y, xv4.z, xv4.w};
        float s[4];
        #pragma unroll
        for (int k = 0; k < 4; k++) {
            float dd = xv[k] - a[k];
            a[k] = fmaf(al[k], dd, a[k]);              // h_a update
            v[k] = be[k] * fmaf(al[k] * dd, dd, v[k]); // h_v update (>= 0)
            s[k] = fast_sqrt(v[k]);
        }
        __stcs(oa + ooff, make_float4(a[0], a[1], a[2], a[3]));
        __stcs(ov + ooff, make_float4(s[0], s[1], s[2], s[3]));
        ooff += 2 * (CHN / 4);
    }
}

// ---------------------------------------------------------------------------
// Launch
// ---------------------------------------------------------------------------
extern "C" void kernel_launch(void* const* d_in, const int* in_sizes, int n_in,
                              void* d_out, int out_size) {
    const float4* x     = (const float4*)d_in[0];
    const float*  h_a0  = (const float*)d_in[1];
    const float*  h_sd0 = (const float*)d_in[2];
    const float4* alpha = (const float4*)d_in[3];
    float* out = (float*)d_out;

    dim3 gridCN(C_CHUNKS, N_DIM / 4);
    ema_summary<<<gridCN, 128>>>(x, alpha);
    ema_combine<<<CHN / 128, 128>>>(h_a0, h_sd0, (const float*)d_in[3], out);
    ema_output<<<gridCN, 128>>>(x, alpha, (float4*)d_out);
}